// round 10
// baseline (speedup 1.0000x reference)
#include <cuda_runtime.h>
#include <cstdint>

#define N_TOKENS (16*8192)
#define HD       256
#define NEXP     32
#define BATCH    16
#define SEQ      8192
#define TPB      256
#define WARPS    8
#define TOK_PER_TILE 32
#define NTILES   (N_TOKENS/TOK_PER_TILE)   // 4096 warp-tiles
#define NBLK     296                       // 2 x 148 SMs -> exactly 2 blocks/SM
#define NKS      (HD/8)                    // 32 k-steps
// B fragment table: [ks 32][nt 4][split 2][lane 32][r 2] u32 = 64 KB
#define BT_IDX(ks,nt,s,t,r) (((((ks)*4+(nt))*2+(s))*32+(t))*2+(r))
#define SMEM_DYN (NKS*4*2*32*2*4)

__device__ float g_ssum[BATCH*NEXP];
__device__ int   g_cnt [BATCH*NEXP];
__device__ unsigned g_done;

__device__ __forceinline__ uint32_t tf32_hi(float x) {
    uint32_t r; asm("cvt.rna.tf32.f32 %0, %1;" : "=r"(r) : "f"(x)); return r;
}
__device__ __forceinline__ void mma_tf32(float* c,
        uint32_t a0, uint32_t a1, uint32_t a2, uint32_t a3,
        uint32_t b0, uint32_t b1) {
    asm volatile(
        "mma.sync.aligned.m16n8k8.row.col.f32.tf32.tf32.f32 "
        "{%0,%1,%2,%3}, {%4,%5,%6,%7}, {%8,%9}, {%0,%1,%2,%3};"
        : "+f"(c[0]), "+f"(c[1]), "+f"(c[2]), "+f"(c[3])
        : "r"(a0), "r"(a1), "r"(a2), "r"(a3), "r"(b0), "r"(b1));
}

extern __shared__ uint32_t Btab[];

__global__ void __launch_bounds__(TPB, 2)
gate_kernel(const float* __restrict__ hs, const float* __restrict__ w,
            float* __restrict__ out)
{
    __shared__ float s_aux[2][NEXP];   // two batch rows (block range spans <= 2)
    __shared__ int   s_cnt[2][NEXP];
    __shared__ int   s_last;

    const int tid  = threadIdx.x;
    const int lane = tid & 31;
    const int warp = tid >> 5;
    const int lq   = lane & 3;     // quad col
    const int lr   = lane >> 2;    // quad row (0..7)

    // Bresenham tile range for this block
    const int t_start = (int)(((long long)blockIdx.x * NTILES) / NBLK);
    const int t_end   = (int)(((long long)(blockIdx.x + 1) * NTILES) / NBLK);
    const int b_base  = t_start >> 8;   // 256 tiles per batch row

    // ---- build B fragment table (hi/lo tf32, k-permuted to match A loads) ----
    #pragma unroll 4
    for (int it = 0; it < NEXP; it++) {
        float v = w[it*HD + tid];          // n = it, k = tid (coalesced)
        uint32_t hi = tf32_hi(v);
        float lo = v - __uint_as_float(hi);
        int k = tid, n = it;
        int ks = k >> 3, kk = k & 7;
        int c = kk >> 1, r = kk & 1;
        int nt = n >> 3, t = (n & 7)*4 + c;
        Btab[BT_IDX(ks, nt, 0, t, r)] = hi;
        Btab[BT_IDX(ks, nt, 1, t, r)] = __float_as_uint(lo);
    }
    if (tid < 2*NEXP) { s_aux[tid>>5][tid&31] = 0.0f; s_cnt[tid>>5][tid&31] = 0; }
    __syncthreads();

    for (int tile = t_start + warp; tile < t_end; tile += WARPS) {
        const int tb  = tile * TOK_PER_TILE;
        const int bi  = (tile >> 8) - b_base;   // 0 or 1
        // row pointers for this thread's 4 fragment rows (pre-offset by quad col)
        const float2* rp[4];
        #pragma unroll
        for (int i = 0; i < 4; i++)
            rp[i] = (const float2*)(hs + (size_t)(tb + i*8 + lr)*HD) + lq;

        float acc[2][4][4];
        #pragma unroll
        for (int mt = 0; mt < 2; mt++)
            #pragma unroll
            for (int nt = 0; nt < 4; nt++)
                #pragma unroll
                for (int i = 0; i < 4; i++) acc[mt][nt][i] = 0.0f;

        #pragma unroll 2
        for (int g = 0; g < NKS/4; g++) {
            // batch A loads for 4 k-steps: 16 LDG.64, full-line coverage
            float2 av[4][4];                 // [kstep][row]
            #pragma unroll
            for (int kk = 0; kk < 4; kk++)
                #pragma unroll
                for (int i = 0; i < 4; i++)
                    av[kk][i] = rp[i][(g*4 + kk)*4];

            #pragma unroll
            for (int kk = 0; kk < 4; kk++) {
                const int ks = g*4 + kk;
                uint32_t ah[4][2], al[4][2];
                #pragma unroll
                for (int i = 0; i < 4; i++) {
                    ah[i][0] = tf32_hi(av[kk][i].x);
                    ah[i][1] = tf32_hi(av[kk][i].y);
                    al[i][0] = __float_as_uint(av[kk][i].x - __uint_as_float(ah[i][0]));
                    al[i][1] = __float_as_uint(av[kk][i].y - __uint_as_float(ah[i][1]));
                }
                #pragma unroll
                for (int nt = 0; nt < 4; nt++) {
                    uint2 bh = *(const uint2*)&Btab[BT_IDX(ks, nt, 0, lane, 0)];
                    uint2 bl = *(const uint2*)&Btab[BT_IDX(ks, nt, 1, lane, 0)];
                    #pragma unroll
                    for (int mt = 0; mt < 2; mt++) {
                        const int r0 = mt*2, r1 = mt*2 + 1;
                        mma_tf32(acc[mt][nt], ah[r0][0], ah[r1][0], ah[r0][1], ah[r1][1], bh.x, bh.y);
                        mma_tf32(acc[mt][nt], ah[r0][0], ah[r1][0], ah[r0][1], ah[r1][1], bl.x, bl.y);
                        mma_tf32(acc[mt][nt], al[r0][0], al[r1][0], al[r0][1], al[r1][1], bh.x, bh.y);
                    }
                }
            }
        }

        // ---- epilogue: token row (mt*16 + half*8 + lr) logits on quad (lq=0..3) ----
        float aux8[8];
        #pragma unroll
        for (int i = 0; i < 8; i++) aux8[i] = 0.0f;

        #pragma unroll
        for (int mt = 0; mt < 2; mt++) {
            #pragma unroll
            for (int half = 0; half < 2; half++) {
                float lg[8];
                #pragma unroll
                for (int nt = 0; nt < 4; nt++) {
                    lg[nt*2]   = acc[mt][nt][half*2];
                    lg[nt*2+1] = acc[mt][nt][half*2+1];
                }
                float m = lg[0]; int a = lq*2;
                #pragma unroll
                for (int i = 1; i < 8; i++) {
                    int e = (i>>1)*8 + lq*2 + (i&1);
                    if (lg[i] > m) { m = lg[i]; a = e; }
                }
                #pragma unroll
                for (int d = 1; d <= 2; d <<= 1) {
                    float om = __shfl_xor_sync(0xffffffffu, m, d);
                    int   oa = __shfl_xor_sync(0xffffffffu, a, d);
                    if (om > m || (om == m && oa < a)) { m = om; a = oa; }
                }
                float ex[8]; float s = 0.0f;
                #pragma unroll
                for (int i = 0; i < 8; i++) { ex[i] = expf(lg[i] - m); s += ex[i]; }
                #pragma unroll
                for (int d = 1; d <= 2; d <<= 1) s += __shfl_xor_sync(0xffffffffu, s, d);
                float inv = 1.0f / s;
                #pragma unroll
                for (int i = 0; i < 8; i++) aux8[i] += ex[i] * inv;
                if (lq == 0) {
                    int gidx = tb + mt*16 + half*8 + lr;
                    out[gidx]            = (float)a;
                    out[N_TOKENS + gidx] = inv;      // top-1 score, SCALING=1
                    atomicAdd(&s_cnt[bi][a], 1);
                }
            }
        }

        // per-tile aux: reduce across lanes with same lq (xor 4,8,16), then smem atomics
        #pragma unroll
        for (int i = 0; i < 8; i++) {
            float v = aux8[i];
            #pragma unroll
            for (int d = 4; d <= 16; d <<= 1) v += __shfl_xor_sync(0xffffffffu, v, d);
            if (lane < 4) atomicAdd(&s_aux[bi][(i>>1)*8 + lane*2 + (i&1)], v);
        }
    }
    __syncthreads();

    // flush (two possible batch rows)
    if (tid < 2*NEXP) {
        int r = tid >> 5, e = tid & 31;
        int br = b_base + r;
        if (br < BATCH) {
            atomicAdd(&g_ssum[br*NEXP + e], s_aux[r][e]);
            atomicAdd(&g_cnt [br*NEXP + e], s_cnt[r][e]);
        }
    }

    // ---- last block: finalize aux loss, reset globals ----
    if (tid == 0) {
        __threadfence();
        unsigned ticket = atomicAdd(&g_done, 1u);
        s_last = (ticket == (unsigned)(gridDim.x - 1));
    }
    __syncthreads();
    if (s_last) {
        __threadfence();
        __shared__ float red[TPB];
        float term = 0.0f;
        #pragma unroll
        for (int i = tid; i < BATCH*NEXP; i += TPB)
            term += ((float)g_cnt[i] * (1.0f/256.0f)) * (g_ssum[i] * (1.0f/(float)SEQ));
        red[tid] = term;
        __syncthreads();
        #pragma unroll
        for (int s2 = TPB/2; s2 > 0; s2 >>= 1) {
            if (tid < s2) red[tid] += red[tid + s2];
            __syncthreads();
        }
        if (tid == 0) out[2*N_TOKENS] = red[0] * (0.001f / (float)BATCH);
        #pragma unroll
        for (int i = tid; i < BATCH*NEXP; i += TPB) { g_ssum[i] = 0.0f; g_cnt[i] = 0; }
        if (tid == 0) g_done = 0u;
    }
}

extern "C" void kernel_launch(void* const* d_in, const int* in_sizes, int n_in,
                              void* d_out, int out_size) {
    const float* hs = (const float*)d_in[0];
    const float* w  = (const float*)d_in[1];
    float* out = (float*)d_out;
    cudaFuncSetAttribute(gate_kernel, cudaFuncAttributeMaxDynamicSharedMemorySize, SMEM_DYN);
    gate_kernel<<<NBLK, TPB, SMEM_DYN>>>(hs, w, out);
}

// round 11
// speedup vs baseline: 1.0935x; 1.0935x over previous
#include <cuda_runtime.h>
#include <cstdint>

#define N_TOKENS (16*8192)
#define HD       256
#define NEXP     32
#define BATCH    16
#define SEQ      8192
#define TPB      256
#define WARPS    8
#define TOK_PER_TILE 32
#define NTILES   (N_TOKENS/TOK_PER_TILE)   // 4096 warp-tiles
#define NBLK     296                       // 2 x 148 SMs
#define NH       (HD/16)                   // 16 h-groups (16 k each)
// B fragment table: [ks 32][nt 4][lane 32] x uint4 {bh_r0, bh_r1, bl_r0, bl_r1} = 64 KB
#define SMEM_DYN (32*4*32*4*4)

__device__ float g_ssum[BATCH*NEXP];
__device__ int   g_cnt [BATCH*NEXP];
__device__ unsigned g_done;

__device__ __forceinline__ uint32_t tf32_hi(float x) {
    uint32_t r; asm("cvt.rna.tf32.f32 %0, %1;" : "=r"(r) : "f"(x)); return r;
}
__device__ __forceinline__ void mma_tf32(float* c,
        uint32_t a0, uint32_t a1, uint32_t a2, uint32_t a3,
        uint32_t b0, uint32_t b1) {
    asm volatile(
        "mma.sync.aligned.m16n8k8.row.col.f32.tf32.tf32.f32 "
        "{%0,%1,%2,%3}, {%4,%5,%6,%7}, {%8,%9}, {%0,%1,%2,%3};"
        : "+f"(c[0]), "+f"(c[1]), "+f"(c[2]), "+f"(c[3])
        : "r"(a0), "r"(a1), "r"(a2), "r"(a3), "r"(b0), "r"(b1));
}

extern __shared__ uint32_t Btab[];

__global__ void __launch_bounds__(TPB, 2)
gate_kernel(const float* __restrict__ hs, const float* __restrict__ w,
            float* __restrict__ out)
{
    __shared__ float s_aux[2][NEXP];
    __shared__ int   s_cnt[2][NEXP];
    __shared__ int   s_last;

    const int tid  = threadIdx.x;
    const int lane = tid & 31;
    const int warp = tid >> 5;
    const int lq   = lane & 3;
    const int lr   = lane >> 2;

    const int t_start = (int)(((long long)blockIdx.x * NTILES) / NBLK);
    const int t_end   = (int)(((long long)(blockIdx.x + 1) * NTILES) / NBLK);
    const int b_base  = t_start >> 8;

    // ---- build B fragment table (hi/lo tf32, float4-era k-permutation) ----
    // physical k: h=k>>4, j=k&15, q=j>>2, rr=j&3 -> kstep=2h+(rr>>1), col=q, r=rr&1
    #pragma unroll 4
    for (int it = 0; it < NEXP; it++) {
        float v = w[it*HD + tid];
        uint32_t hi = tf32_hi(v);
        float lo = v - __uint_as_float(hi);
        int k = tid;
        int h = k >> 4, j = k & 15, q = j >> 2, rr = j & 3;
        int ks = 2*h + (rr >> 1), r = rr & 1;
        int nt = it >> 3, t = (it & 7)*4 + q;
        int idx = ((ks*4 + nt)*32 + t)*4;
        Btab[idx + r]     = hi;
        Btab[idx + 2 + r] = __float_as_uint(lo);
    }
    if (tid < 2*NEXP) { s_aux[tid>>5][tid&31] = 0.0f; s_cnt[tid>>5][tid&31] = 0; }
    __syncthreads();

    for (int tile = t_start + warp; tile < t_end; tile += WARPS) {
        const int tb = tile * TOK_PER_TILE;
        const int bi = (tile >> 8) - b_base;
        const float4* rp[4];
        #pragma unroll
        for (int i = 0; i < 4; i++)
            rp[i] = (const float4*)(hs + (size_t)(tb + i*8 + lr)*HD);

        float acc[2][4][4];
        #pragma unroll
        for (int mt = 0; mt < 2; mt++)
            #pragma unroll
            for (int nt = 0; nt < 4; nt++)
                #pragma unroll
                for (int i = 0; i < 4; i++) acc[mt][nt][i] = 0.0f;

        float4 cur[4], nxt[4];
        #pragma unroll
        for (int i = 0; i < 4; i++) cur[i] = rp[i][lq];

        #pragma unroll 2
        for (int h = 0; h < NH; h++) {
            if (h + 1 < NH) {                 // distance-1 prefetch (in flight over MMAs)
                #pragma unroll
                for (int i = 0; i < 4; i++) nxt[i] = rp[i][(h+1)*4 + lq];
            }
            #pragma unroll
            for (int s01 = 0; s01 < 2; s01++) {
                uint32_t ah[4][2], al[4][2];
                #pragma unroll
                for (int i = 0; i < 4; i++) {
                    float f0 = s01 ? cur[i].z : cur[i].x;
                    float f1 = s01 ? cur[i].w : cur[i].y;
                    ah[i][0] = tf32_hi(f0);
                    ah[i][1] = tf32_hi(f1);
                    al[i][0] = __float_as_uint(f0 - __uint_as_float(ah[i][0]));
                    al[i][1] = __float_as_uint(f1 - __uint_as_float(ah[i][1]));
                }
                const uint32_t* bt = &Btab[((8*h + s01*4)*32 + lane)*4];
                #pragma unroll
                for (int nt = 0; nt < 4; nt++) {
                    uint4 bb = *(const uint4*)(bt + nt*128);
                    #pragma unroll
                    for (int mt = 0; mt < 2; mt++) {
                        const int r0 = mt*2, r1 = mt*2 + 1;
                        mma_tf32(acc[mt][nt], ah[r0][0], ah[r1][0], ah[r0][1], ah[r1][1], bb.x, bb.y);
                        mma_tf32(acc[mt][nt], ah[r0][0], ah[r1][0], ah[r0][1], ah[r1][1], bb.z, bb.w);
                        mma_tf32(acc[mt][nt], al[r0][0], al[r1][0], al[r0][1], al[r1][1], bb.x, bb.y);
                    }
                }
            }
            #pragma unroll
            for (int i = 0; i < 4; i++) cur[i] = nxt[i];
        }

        // ---- epilogue: token row (mt*16 + half*8 + lr), logits across quad ----
        float aux8[8];
        #pragma unroll
        for (int i = 0; i < 8; i++) aux8[i] = 0.0f;

        #pragma unroll
        for (int mt = 0; mt < 2; mt++) {
            #pragma unroll
            for (int half = 0; half < 2; half++) {
                float lg[8];
                #pragma unroll
                for (int nt = 0; nt < 4; nt++) {
                    lg[nt*2]   = acc[mt][nt][half*2];
                    lg[nt*2+1] = acc[mt][nt][half*2+1];
                }
                float m = lg[0]; int a = lq*2;
                #pragma unroll
                for (int i = 1; i < 8; i++) {
                    int e = (i>>1)*8 + lq*2 + (i&1);
                    if (lg[i] > m) { m = lg[i]; a = e; }
                }
                #pragma unroll
                for (int d = 1; d <= 2; d <<= 1) {
                    float om = __shfl_xor_sync(0xffffffffu, m, d);
                    int   oa = __shfl_xor_sync(0xffffffffu, a, d);
                    if (om > m || (om == m && oa < a)) { m = om; a = oa; }
                }
                float ex[8]; float s = 0.0f;
                #pragma unroll
                for (int i = 0; i < 8; i++) { ex[i] = __expf(lg[i] - m); s += ex[i]; }
                #pragma unroll
                for (int d = 1; d <= 2; d <<= 1) s += __shfl_xor_sync(0xffffffffu, s, d);
                float inv = 1.0f / s;
                #pragma unroll
                for (int i = 0; i < 8; i++) aux8[i] += ex[i] * inv;
                if (lq == 0) {
                    int gidx = tb + mt*16 + half*8 + lr;
                    out[gidx]            = (float)a;
                    out[N_TOKENS + gidx] = inv;
                    atomicAdd(&s_cnt[bi][a], 1);
                }
            }
        }

        #pragma unroll
        for (int i = 0; i < 8; i++) {
            float v = aux8[i];
            #pragma unroll
            for (int d = 4; d <= 16; d <<= 1) v += __shfl_xor_sync(0xffffffffu, v, d);
            if (lane < 4) atomicAdd(&s_aux[bi][(i>>1)*8 + lane*2 + (i&1)], v);
        }
    }
    __syncthreads();

    if (tid < 2*NEXP) {
        int r = tid >> 5, e = tid & 31;
        int br = b_base + r;
        if (br < BATCH) {
            atomicAdd(&g_ssum[br*NEXP + e], s_aux[r][e]);
            atomicAdd(&g_cnt [br*NEXP + e], s_cnt[r][e]);
        }
    }

    // ---- last block: finalize aux loss, reset globals ----
    if (tid == 0) {
        __threadfence();
        unsigned ticket = atomicAdd(&g_done, 1u);
        s_last = (ticket == (unsigned)(gridDim.x - 1));
    }
    __syncthreads();
    if (s_last) {
        __threadfence();
        __shared__ float red[TPB];
        float term = 0.0f;
        #pragma unroll
        for (int i = tid; i < BATCH*NEXP; i += TPB)
            term += ((float)g_cnt[i] * (1.0f/256.0f)) * (g_ssum[i] * (1.0f/(float)SEQ));
        red[tid] = term;
        __syncthreads();
        #pragma unroll
        for (int s2 = TPB/2; s2 > 0; s2 >>= 1) {
            if (tid < s2) red[tid] += red[tid + s2];
            __syncthreads();
        }
        if (tid == 0) out[2*N_TOKENS] = red[0] * (0.001f / (float)BATCH);
        #pragma unroll
        for (int i = tid; i < BATCH*NEXP; i += TPB) { g_ssum[i] = 0.0f; g_cnt[i] = 0; }
        if (tid == 0) g_done = 0u;
    }
}

extern "C" void kernel_launch(void* const* d_in, const int* in_sizes, int n_in,
                              void* d_out, int out_size) {
    const float* hs = (const float*)d_in[0];
    const float* w  = (const float*)d_in[1];
    float* out = (float*)d_out;
    cudaFuncSetAttribute(gate_kernel, cudaFuncAttributeMaxDynamicSharedMemorySize, SMEM_DYN);
    gate_kernel<<<NBLK, TPB, SMEM_DYN>>>(hs, w, out);
}